// round 5
// baseline (speedup 1.0000x reference)
#include <cuda_runtime.h>
#include <cstdint>

#define ZD     128          // z_dim
#define NOUT   1024         // K*RANK
#define NMAT_MAX 65536

// 256 MB scratch for w = z @ W^T + b + 1e-6
__device__ float g_w[(size_t)NMAT_MAX * NOUT];

// ---------------------------------------------------------------------------
// GEMM: g_w[m][n] = sum_k z[m][k] * W[n][k] + b[n] + 1e-6
// Tile: BM=128, BN=128, full K=128 in one pass. 256 threads, 8x8 microtile.
// ---------------------------------------------------------------------------
#define BM 128
#define BN 128
#define SZ 133   // Zs row stride (floats), padded for conflict-free LDS
#define SW 132   // Ws row stride (floats), mult-of-4 for float4 STS

__global__ __launch_bounds__(256) void qr_gemm_kernel(
    const float* __restrict__ Z, const float* __restrict__ W,
    const float* __restrict__ bias)
{
    extern __shared__ float sm[];
    float* Zs = sm;             // [BM][SZ]  (row-major, m x k)
    float* Ws = sm + BM * SZ;   // [BN][SW]  (row-major, n x k)

    const int tid = threadIdx.x;
    const int m0  = blockIdx.x * BM;
    const int n0  = blockIdx.y * BN;

    // Load Z tile: 128 rows x 128 k  (coalesced float4 reads)
    #pragma unroll
    for (int i = 0; i < 16; i++) {
        int f  = tid + i * 256;     // float4 index, 32 per row
        int m  = f >> 5;
        int kq = f & 31;
        float4 v = reinterpret_cast<const float4*>(Z + (size_t)(m0 + m) * ZD)[kq];
        float* d = Zs + m * SZ + kq * 4;
        d[0] = v.x; d[1] = v.y; d[2] = v.z; d[3] = v.w;
    }
    // Load W tile: 128 rows(n) x 128 k
    #pragma unroll
    for (int i = 0; i < 16; i++) {
        int f  = tid + i * 256;
        int n  = f >> 5;
        int kq = f & 31;
        float4 v = reinterpret_cast<const float4*>(W + (size_t)(n0 + n) * ZD)[kq];
        reinterpret_cast<float4*>(Ws + n * SW)[kq] = v;
    }
    __syncthreads();

    const int tx = tid & 15;    // n-group
    const int ty = tid >> 4;    // m-group
    // thread owns rows m0 + ty + 16*i, cols n0 + tx + 16*u  (i,u in 0..7)

    float acc[8][8];
    #pragma unroll
    for (int i = 0; i < 8; i++)
        #pragma unroll
        for (int u = 0; u < 8; u++) acc[i][u] = 0.f;

    #pragma unroll 4
    for (int k = 0; k < ZD; k++) {
        float za[8], wb[8];
        #pragma unroll
        for (int i = 0; i < 8; i++) za[i] = Zs[(ty + 16 * i) * SZ + k];
        #pragma unroll
        for (int u = 0; u < 8; u++) wb[u] = Ws[(tx + 16 * u) * SW + k];
        #pragma unroll
        for (int i = 0; i < 8; i++)
            #pragma unroll
            for (int u = 0; u < 8; u++)
                acc[i][u] = fmaf(za[i], wb[u], acc[i][u]);
    }

    float bb[8];
    #pragma unroll
    for (int u = 0; u < 8; u++) bb[u] = bias[n0 + tx + 16 * u];

    #pragma unroll
    for (int i = 0; i < 8; i++) {
        size_t row = (size_t)(m0 + ty + 16 * i) * NOUT;
        #pragma unroll
        for (int u = 0; u < 8; u++) {
            float c = acc[i][u] + bb[u];   // match reference: (z@W^T + b) ...
            c = c + 1e-6f;                 // ... then + 1e-6
            g_w[row + n0 + tx + 16 * u] = c;
        }
    }
}

// ---------------------------------------------------------------------------
// Batched Householder QR (LAPACK geqrf + org2r convention), warp per matrix.
// Matrix is 64 rows x 16 cols. Lane owns rows 2*lane and 2*lane+1.
// v_j stored in-place in column j (v[j]=1, zeros above), so trailing updates
// and Q formation need no row predicates (v is exactly 0 for rows < j).
// ---------------------------------------------------------------------------
__device__ __forceinline__ float warp_sum(float v) {
    v += __shfl_xor_sync(0xffffffffu, v, 16);
    v += __shfl_xor_sync(0xffffffffu, v, 8);
    v += __shfl_xor_sync(0xffffffffu, v, 4);
    v += __shfl_xor_sync(0xffffffffu, v, 2);
    v += __shfl_xor_sync(0xffffffffu, v, 1);
    return v;
}

__global__ __launch_bounds__(256) void qr_house_kernel(
    float* __restrict__ out, int nmat)
{
    const int gw   = (int)((blockIdx.x * blockDim.x + threadIdx.x) >> 5);
    const int lane = threadIdx.x & 31;
    if (gw >= nmat) return;

    const int r0 = 2 * lane;
    const int r1 = 2 * lane + 1;

    float a0[16], a1[16];
    {
        const float4* src =
            reinterpret_cast<const float4*>(g_w + (size_t)gw * NOUT + lane * 32);
        #pragma unroll
        for (int i = 0; i < 4; i++) {
            float4 t = src[i];
            a0[4*i+0] = t.x; a0[4*i+1] = t.y; a0[4*i+2] = t.z; a0[4*i+3] = t.w;
        }
        #pragma unroll
        for (int i = 0; i < 4; i++) {
            float4 t = src[4 + i];
            a1[4*i+0] = t.x; a1[4*i+1] = t.y; a1[4*i+2] = t.z; a1[4*i+3] = t.w;
        }
    }

    float tau[16];

    // ---- factorization (sgeqrf / slarfg) ----
    #pragma unroll
    for (int j = 0; j < 16; j++) {
        // xnorm^2 over rows j+1..63
        float s = 0.f;
        if (r0 > j) s = fmaf(a0[j], a0[j], s);
        if (r1 > j) s = fmaf(a1[j], a1[j], s);
        s = warp_sum(s);

        // alpha = A[j][j], broadcast from owner lane j/2
        float av    = (j & 1) ? a1[j] : a0[j];
        float alpha = __shfl_sync(0xffffffffu, av, j >> 1);

        float tj, scale;
        if (s == 0.f) {            // LAPACK: xnorm==0 -> H = I
            tj = 0.f; scale = 0.f;
        } else {
            float beta = -copysignf(sqrtf(fmaf(alpha, alpha, s)), alpha);
            tj    = (beta - alpha) / beta;
            scale = 1.f / (alpha - beta);
        }
        tau[j] = tj;

        // build v in column j: rows>j scaled, row j = 1, rows<j = 0
        a0[j] = (r0 > j) ? a0[j] * scale : ((r0 == j) ? 1.f : 0.f);
        a1[j] = (r1 > j) ? a1[j] * scale : ((r1 == j) ? 1.f : 0.f);

        // apply H_j = I - tau v v^T to trailing columns (v==0 above row j)
        #pragma unroll
        for (int c = j + 1; c < 16; c++) {
            float d = fmaf(a0[j], a0[c], a1[j] * a1[c]);
            d = warp_sum(d) * tj;
            a0[c] = fmaf(-d, a0[j], a0[c]);
            a1[c] = fmaf(-d, a1[j], a1[c]);
        }
    }

    // ---- form Q (sorg2r, reflectors applied in reverse) ----
    float q0[16], q1[16];
    #pragma unroll
    for (int c = 0; c < 16; c++) {
        q0[c] = (r0 == c) ? 1.f : 0.f;
        q1[c] = (r1 == c) ? 1.f : 0.f;
    }
    #pragma unroll
    for (int jj = 0; jj < 16; jj++) {
        const int j = 15 - jj;
        const float tj = tau[j];
        #pragma unroll
        for (int c = j; c < 16; c++) {
            float d = fmaf(a0[j], q0[c], a1[j] * q1[c]);
            d = warp_sum(d) * tj;
            q0[c] = fmaf(-d, a0[j], q0[c]);
            q1[c] = fmaf(-d, a1[j], q1[c]);
        }
    }

    // ---- store Q (coalesced: lane writes its 2 rows = 32 floats) ----
    float4* dst = reinterpret_cast<float4*>(out + (size_t)gw * NOUT + lane * 32);
    #pragma unroll
    for (int i = 0; i < 4; i++)
        dst[i] = make_float4(q0[4*i], q0[4*i+1], q0[4*i+2], q0[4*i+3]);
    #pragma unroll
    for (int i = 0; i < 4; i++)
        dst[4 + i] = make_float4(q1[4*i], q1[4*i+1], q1[4*i+2], q1[4*i+3]);
}

// ---------------------------------------------------------------------------
extern "C" void kernel_launch(void* const* d_in, const int* in_sizes, int n_in,
                              void* d_out, int out_size)
{
    const float* z = (const float*)d_in[0];   // [B, 128]
    const float* W = (const float*)d_in[1];   // [1024, 128]
    const float* b = (const float*)d_in[2];   // [1024]
    float* out = (float*)d_out;               // [B, 64, 16]

    const int Bn = in_sizes[0] / ZD;          // 65536

    const size_t smem = (size_t)(BM * SZ + BN * SW) * sizeof(float);
    cudaFuncSetAttribute(qr_gemm_kernel,
                         cudaFuncAttributeMaxDynamicSharedMemorySize, (int)smem);

    dim3 ggrid(Bn / BM, NOUT / BN);
    qr_gemm_kernel<<<ggrid, 256, smem>>>(z, W, b);

    const int blocks = (Bn * 32 + 255) / 256;   // warp per matrix
    qr_house_kernel<<<blocks, 256>>>(out, Bn);
}

// round 14
// speedup vs baseline: 1.0498x; 1.0498x over previous
#include <cuda_runtime.h>
#include <cuda_fp16.h>
#include <cstdint>

#define ZD     128          // z_dim
#define NOUT   1024         // K*RANK
#define NMAT_MAX 65536

// 256 MB scratch for w = z @ W^T + b + 1e-6
__device__ float g_w[(size_t)NMAT_MAX * NOUT];

// ===========================================================================
// GEMM: g_w = z @ W^T + b + 1e-6 via warp-level mma.sync (baseline PTX,
// runs as HMMA on sm_103). fp16 two-word split, fp32 accumulate:
//     z*W ~= zhi*Whi + zlo*Whi + zhi*Wlo      (lo*lo dropped, ~2^-22 rel)
// CTA tile M=128 x N=128, full K=128 in smem. 8 warps as 4(M) x 2(N);
// warp tile 32x64 = 2 m-frags x 8 n-frags of m16n8k16.
// ===========================================================================
#define SA 136   // smem row stride in halves (272B: rows offset 4 banks, conflict-free)

__device__ __forceinline__ void mma16816(float* c, const uint32_t* a, const uint32_t* b) {
    asm volatile(
        "mma.sync.aligned.m16n8k16.row.col.f32.f16.f16.f32 "
        "{%0,%1,%2,%3}, {%4,%5,%6,%7}, {%8,%9}, {%0,%1,%2,%3};"
        : "+f"(c[0]), "+f"(c[1]), "+f"(c[2]), "+f"(c[3])
        : "r"(a[0]), "r"(a[1]), "r"(a[2]), "r"(a[3]), "r"(b[0]), "r"(b[1]));
}

__device__ __forceinline__ uint2 split_pack(float4 v, uint2& lo_out) {
    __half h0 = __float2half_rn(v.x), h1 = __float2half_rn(v.y);
    __half h2 = __float2half_rn(v.z), h3 = __float2half_rn(v.w);
    __half l0 = __float2half_rn(v.x - __half2float(h0));
    __half l1 = __float2half_rn(v.y - __half2float(h1));
    __half l2 = __float2half_rn(v.z - __half2float(h2));
    __half l3 = __float2half_rn(v.w - __half2float(h3));
    __half2 ph0 = __halves2half2(h0, h1), ph1 = __halves2half2(h2, h3);
    __half2 pl0 = __halves2half2(l0, l1), pl1 = __halves2half2(l2, l3);
    uint2 hi;
    hi.x = *reinterpret_cast<uint32_t*>(&ph0);
    hi.y = *reinterpret_cast<uint32_t*>(&ph1);
    lo_out.x = *reinterpret_cast<uint32_t*>(&pl0);
    lo_out.y = *reinterpret_cast<uint32_t*>(&pl1);
    return hi;
}

__global__ __launch_bounds__(256) void qr_gemm_mma(
    const float* __restrict__ Z, const float* __restrict__ W,
    const float* __restrict__ bias)
{
    extern __shared__ char smem[];
    __half* Ah = reinterpret_cast<__half*>(smem);   // [128][SA]
    __half* Al = Ah + 128 * SA;
    __half* Bh = Al + 128 * SA;
    __half* Bl = Bh + 128 * SA;
    float*  bs = reinterpret_cast<float*>(Bl + 128 * SA);   // 128 floats

    const int tid  = threadIdx.x;
    const int wid  = tid >> 5;
    const int lane = tid & 31;
    const int n0   = blockIdx.x * 128;   // n-tile fastest -> z tile L2 reuse
    const int m0   = blockIdx.y * 128;

    if (tid < 128) bs[tid] = bias[n0 + tid];

    // ---- load + fp16-split z tile: 128 rows x 128 k (float4 coalesced) ----
    #pragma unroll
    for (int it = 0; it < 16; it++) {
        int f   = tid + it * 256;
        int row = f >> 5;
        int kq  = f & 31;                 // float4 index within row
        float4 v = reinterpret_cast<const float4*>(Z + (size_t)(m0 + row) * ZD)[kq];
        uint2 lo, hi = split_pack(v, lo);
        *reinterpret_cast<uint2*>(Ah + row * SA + kq * 4) = hi;
        *reinterpret_cast<uint2*>(Al + row * SA + kq * 4) = lo;
    }
    // ---- load + fp16-split W tile: 128 rows(n) x 128 k ----
    #pragma unroll
    for (int it = 0; it < 16; it++) {
        int f   = tid + it * 256;
        int row = f >> 5;
        int kq  = f & 31;
        float4 v = reinterpret_cast<const float4*>(W + (size_t)(n0 + row) * ZD)[kq];
        uint2 lo, hi = split_pack(v, lo);
        *reinterpret_cast<uint2*>(Bh + row * SA + kq * 4) = hi;
        *reinterpret_cast<uint2*>(Bl + row * SA + kq * 4) = lo;
    }
    __syncthreads();

    const int gid = lane >> 2;            // 0..7
    const int tig = lane & 3;             // 0..3
    const int wm  = (wid & 3) * 32;       // warp m-offset
    const int wn  = (wid >> 2) * 64;      // warp n-offset

    float c[2][8][4];
    #pragma unroll
    for (int i = 0; i < 2; i++)
        #pragma unroll
        for (int j = 0; j < 8; j++)
            #pragma unroll
            for (int q = 0; q < 4; q++) c[i][j][q] = 0.f;

    #pragma unroll
    for (int ks = 0; ks < 8; ks++) {
        const int k0 = ks * 16;
        uint32_t ah[2][4], al[2][4];
        #pragma unroll
        for (int mf = 0; mf < 2; mf++) {
            int r = wm + mf * 16 + gid;
            ah[mf][0] = *reinterpret_cast<uint32_t*>(Ah + (r)     * SA + k0 + tig * 2);
            ah[mf][1] = *reinterpret_cast<uint32_t*>(Ah + (r + 8) * SA + k0 + tig * 2);
            ah[mf][2] = *reinterpret_cast<uint32_t*>(Ah + (r)     * SA + k0 + tig * 2 + 8);
            ah[mf][3] = *reinterpret_cast<uint32_t*>(Ah + (r + 8) * SA + k0 + tig * 2 + 8);
            al[mf][0] = *reinterpret_cast<uint32_t*>(Al + (r)     * SA + k0 + tig * 2);
            al[mf][1] = *reinterpret_cast<uint32_t*>(Al + (r + 8) * SA + k0 + tig * 2);
            al[mf][2] = *reinterpret_cast<uint32_t*>(Al + (r)     * SA + k0 + tig * 2 + 8);
            al[mf][3] = *reinterpret_cast<uint32_t*>(Al + (r + 8) * SA + k0 + tig * 2 + 8);
        }
        #pragma unroll
        for (int nh = 0; nh < 2; nh++) {
            uint32_t bb[4][2];
            // Bhi frags for 4 n-tiles
            #pragma unroll
            for (int nf = 0; nf < 4; nf++) {
                int n = wn + nh * 32 + nf * 8 + gid;
                bb[nf][0] = *reinterpret_cast<uint32_t*>(Bh + n * SA + k0 + tig * 2);
                bb[nf][1] = *reinterpret_cast<uint32_t*>(Bh + n * SA + k0 + tig * 2 + 8);
            }
            #pragma unroll
            for (int mf = 0; mf < 2; mf++)
                #pragma unroll
                for (int nf = 0; nf < 4; nf++)
                    mma16816(c[mf][nh * 4 + nf], ah[mf], bb[nf]);   // hi*hi
            #pragma unroll
            for (int mf = 0; mf < 2; mf++)
                #pragma unroll
                for (int nf = 0; nf < 4; nf++)
                    mma16816(c[mf][nh * 4 + nf], al[mf], bb[nf]);   // lo*hi
            // Blo frags (reuse regs)
            #pragma unroll
            for (int nf = 0; nf < 4; nf++) {
                int n = wn + nh * 32 + nf * 8 + gid;
                bb[nf][0] = *reinterpret_cast<uint32_t*>(Bl + n * SA + k0 + tig * 2);
                bb[nf][1] = *reinterpret_cast<uint32_t*>(Bl + n * SA + k0 + tig * 2 + 8);
            }
            #pragma unroll
            for (int mf = 0; mf < 2; mf++)
                #pragma unroll
                for (int nf = 0; nf < 4; nf++)
                    mma16816(c[mf][nh * 4 + nf], ah[mf], bb[nf]);   // hi*lo
        }
    }

    // ---- epilogue: + bias + 1e-6, float2 stores ----
    #pragma unroll
    for (int mf = 0; mf < 2; mf++) {
        int row = m0 + wm + mf * 16 + gid;
        #pragma unroll
        for (int nf = 0; nf < 8; nf++) {
            int ncol = wn + nf * 8 + tig * 2;
            float b0 = bs[ncol], b1 = bs[ncol + 1];
            float* o0 = g_w + (size_t)row * NOUT + n0 + ncol;
            float* o1 = o0 + 8 * NOUT;
            float2 v0 = {(c[mf][nf][0] + b0) + 1e-6f, (c[mf][nf][1] + b1) + 1e-6f};
            float2 v1 = {(c[mf][nf][2] + b0) + 1e-6f, (c[mf][nf][3] + b1) + 1e-6f};
            *reinterpret_cast<float2*>(o0) = v0;
            *reinterpret_cast<float2*>(o1) = v1;
        }
    }
}

// ===========================================================================
// Batched Householder QR (LAPACK geqrf + org2r), 2 matrices per warp.
// 16 lanes per matrix (half h = lane>>4, s = lane&15); lane owns rows
// s, s+16, s+32, s+48. Reductions: 4 SHFL.BFLY (offsets 1,2,4,8) stay inside
// each 16-lane half -> one shuffle instruction serves both matrices.
// Q is formed in-place over A's registers (v_j dies exactly when q_j is born).
// ===========================================================================
__device__ __forceinline__ float half_sum(float v) {
    v += __shfl_xor_sync(0xffffffffu, v, 8);
    v += __shfl_xor_sync(0xffffffffu, v, 4);
    v += __shfl_xor_sync(0xffffffffu, v, 2);
    v += __shfl_xor_sync(0xffffffffu, v, 1);
    return v;
}

__global__ __launch_bounds__(256) void qr_house_kernel(
    float* __restrict__ out, int nmat)
{
    const int warp = (int)((blockIdx.x * blockDim.x + threadIdx.x) >> 5);
    const int lane = threadIdx.x & 31;
    const int h    = lane >> 4;
    const int s    = lane & 15;
    const int mat  = 2 * warp + h;
    if (mat >= nmat) return;        // nmat even -> warp-uniform

    float a[4][16];
    {
        const float* src = g_w + (size_t)mat * NOUT;
        #pragma unroll
        for (int i = 0; i < 4; i++) {
            const float4* p = reinterpret_cast<const float4*>(src + (s + 16*i) * 16);
            #pragma unroll
            for (int q = 0; q < 4; q++) {
                float4 t = p[q];
                a[i][4*q+0] = t.x; a[i][4*q+1] = t.y;
                a[i][4*q+2] = t.z; a[i][4*q+3] = t.w;
            }
        }
    }

    float tau[16];

    // ---- factorization (sgeqrf / slarfg convention) ----
    #pragma unroll
    for (int j = 0; j < 16; j++) {
        float ss = (s > j) ? a[0][j] * a[0][j] : 0.f;
        #pragma unroll
        for (int i = 1; i < 4; i++) ss = fmaf(a[i][j], a[i][j], ss);
        ss = half_sum(ss);

        float alpha = __shfl_sync(0xffffffffu, a[0][j], (lane & 16) | j);

        float tj, scale;
        if (ss == 0.f) { tj = 0.f; scale = 0.f; }   // LAPACK: xnorm==0 -> H=I
        else {
            float beta = -copysignf(sqrtf(fmaf(alpha, alpha, ss)), alpha);
            tj    = (beta - alpha) / beta;
            scale = 1.f / (alpha - beta);
        }
        tau[j] = tj;

        a[0][j] = (s > j) ? a[0][j] * scale : ((s == j) ? 1.f : 0.f);
        #pragma unroll
        for (int i = 1; i < 4; i++) a[i][j] *= scale;

        #pragma unroll
        for (int c = j + 1; c < 16; c++) {
            float d = a[0][j] * a[0][c];
            #pragma unroll
            for (int i = 1; i < 4; i++) d = fmaf(a[i][j], a[i][c], d);
            d = half_sum(d) * tj;
            #pragma unroll
            for (int i = 0; i < 4; i++) a[i][c] = fmaf(-d, a[i][j], a[i][c]);
        }
    }

    // ---- form Q (sorg2r, backward), q_c overwrites a[.][c] ----
    #pragma unroll
    for (int jj = 0; jj < 16; jj++) {
        const int j = 15 - jj;
        const float tj = tau[j];
        float v[4];
        #pragma unroll
        for (int i = 0; i < 4; i++) v[i] = a[i][j];
        // q_j = e_j - tau_j * v_j
        #pragma unroll
        for (int i = 0; i < 4; i++) a[i][j] = -tj * v[i];
        if (s == j) a[0][j] += 1.f;
        #pragma unroll
        for (int c = j + 1; c < 16; c++) {
            float d = v[0] * a[0][c];
            #pragma unroll
            for (int i = 1; i < 4; i++) d = fmaf(v[i], a[i][c], d);
            d = half_sum(d) * tj;
            #pragma unroll
            for (int i = 0; i < 4; i++) a[i][c] = fmaf(-d, v[i], a[i][c]);
        }
    }

    // ---- store Q ----
    {
        float* dst = out + (size_t)mat * NOUT;
        #pragma unroll
        for (int i = 0; i < 4; i++) {
            float4* p = reinterpret_cast<float4*>(dst + (s + 16*i) * 16);
            #pragma unroll
            for (int q = 0; q < 4; q++)
                p[q] = make_float4(a[i][4*q+0], a[i][4*q+1],
                                   a[i][4*q+2], a[i][4*q+3]);
        }
    }
}

// ---------------------------------------------------------------------------
extern "C" void kernel_launch(void* const* d_in, const int* in_sizes, int n_in,
                              void* d_out, int out_size)
{
    const float* z = (const float*)d_in[0];   // [B, 128]
    const float* W = (const float*)d_in[1];   // [1024, 128]
    const float* b = (const float*)d_in[2];   // [1024]
    float* out = (float*)d_out;               // [B, 64, 16]

    const int Bn = in_sizes[0] / ZD;          // 65536

    const int smem = 4 * 128 * SA * (int)sizeof(__half) + 128 * (int)sizeof(float);
    cudaFuncSetAttribute(qr_gemm_mma,
                         cudaFuncAttributeMaxDynamicSharedMemorySize, smem);

    dim3 ggrid(NOUT / 128, Bn / 128);         // x = n-tiles (8), y = m-tiles (512)
    qr_gemm_mma<<<ggrid, 256, smem>>>(z, W, b);

    const int warps  = Bn / 2;                // 2 matrices per warp
    const int blocks = (warps * 32 + 255) / 256;
    qr_house_kernel<<<blocks, 256>>>(out, Bn);
}